// round 1
// baseline (speedup 1.0000x reference)
#include <cuda_runtime.h>
#include <cuda_bf16.h>

#define BATCH 2
#define MDIM 768
#define NDIM 512
#define MN (MDIM*NDIM)

static __device__ __constant__ float EPS_INV = 20.0f;   // 1/0.05
#define AW (1.0f/768.0f)
#define BW (1.0f/512.0f)

// ---------------- device scratch (no allocations allowed) ----------------
__device__ float g_P [BATCH*MN];
__device__ float g_Km[BATCH*MN];
__device__ float g_T [BATCH*MN];
__device__ float g_s [BATCH*MDIM];
__device__ float g_t [BATCH*NDIM];
__device__ float g_rm[BATCH*MDIM];
__device__ float g_cm[BATCH*NDIM];
__device__ float g_t1[BATCH*MDIM];
__device__ float g_t2[BATCH*NDIM];
__device__ float g_acc[BATCH*4];   // [b*4+0]=t1c, +1=t2c, +2=cross

// ---------------- small kernels ----------------
__global__ void pinit_kernel() {
    int idx = blockIdx.x*256 + threadIdx.x;
    if (idx < BATCH*MN) g_P[idx] = AW*BW;
}

// row sums of P: g_rm[b*M+i] = sum_j P[b,i,j]  (warp per row)
__global__ void rowsumP_kernel() {
    int gw = (blockIdx.x*blockDim.x + threadIdx.x) >> 5;
    int lane = threadIdx.x & 31;
    if (gw >= BATCH*MDIM) return;
    const float* rp = g_P + (long)gw*NDIM;
    float s = 0.f;
    for (int j = lane; j < NDIM; j += 32) s += rp[j];
    #pragma unroll
    for (int o = 16; o; o >>= 1) s += __shfl_xor_sync(0xffffffffu, s, o);
    if (!lane) g_rm[gw] = s;
}

// col sums of P: g_cm[b*N+j] = sum_i P[b,i,j]
__global__ void colsumP_kernel() {
    int j = blockIdx.x*32 + threadIdx.x;
    int b = blockIdx.y;
    const float* Pb = g_P + (long)b*MN;
    float acc = 0.f;
    for (int i = threadIdx.y; i < MDIM; i += 8)
        acc += Pb[(long)i*NDIM + j];
    __shared__ float sm[8][33];
    sm[threadIdx.y][threadIdx.x] = acc;
    __syncthreads();
    if (threadIdx.y == 0) {
        float s = 0.f;
        #pragma unroll
        for (int r = 0; r < 8; r++) s += sm[r][threadIdx.x];
        g_cm[b*NDIM + j] = s;
    }
}

// WHICH=0: g_t1[b*M+i] = sum_k D1[b,i,k]^2 * g_rm[b,k]   (K=M)
// WHICH=1: g_t2[b*N+j] = sum_l D2[b,j,l]^2 * g_cm[b,l]   (K=N)
template<int WHICH>
__global__ void sqmv_kernel(const float* __restrict__ Mat) {
    constexpr int ROWS = (WHICH == 0) ? MDIM : NDIM;
    constexpr int KD   = (WHICH == 0) ? MDIM : NDIM;
    int gw = (blockIdx.x*blockDim.x + threadIdx.x) >> 5;
    int lane = threadIdx.x & 31;
    if (gw >= BATCH*ROWS) return;
    int b = gw / ROWS;
    const float* rp = Mat + (long)gw*KD;
    const float* vb = (WHICH == 0 ? g_rm : g_cm) + (long)b*KD;
    float s = 0.f;
    for (int k = lane; k < KD; k += 32) { float m = rp[k]; s += m*m*vb[k]; }
    #pragma unroll
    for (int o = 16; o; o >>= 1) s += __shfl_xor_sync(0xffffffffu, s, o);
    if (!lane) { if (WHICH == 0) g_t1[gw] = s; else g_t2[gw] = s; }
}

__global__ void vinit_kernel() {
    int idx = blockIdx.x*256 + threadIdx.x;
    if (idx < BATCH*NDIM) g_t[idx] = 1.0f;
}

// s_i = a / sum_j K[i,j] * t_j   (warp per row)
__global__ void uupdate_kernel() {
    int gw = (blockIdx.x*blockDim.x + threadIdx.x) >> 5;
    int lane = threadIdx.x & 31;
    if (gw >= BATCH*MDIM) return;
    int b = gw / MDIM;
    const float* Kr = g_Km + (long)gw*NDIM;
    const float* tb = g_t + (long)b*NDIM;
    float s = 0.f;
    for (int j = lane; j < NDIM; j += 32) s += Kr[j]*tb[j];
    #pragma unroll
    for (int o = 16; o; o >>= 1) s += __shfl_xor_sync(0xffffffffu, s, o);
    if (!lane) g_s[gw] = AW / s;
}

// t_j = b / sum_i K[i,j] * s_i   (coalesced column reduction)
__global__ void vupdate_kernel() {
    int j = blockIdx.x*32 + threadIdx.x;
    int b = blockIdx.y;
    const float* Kb = g_Km + (long)b*MN;
    const float* sb = g_s + (long)b*MDIM;
    float acc = 0.f;
    for (int i = threadIdx.y; i < MDIM; i += 8)
        acc += Kb[(long)i*NDIM + j] * sb[i];
    __shared__ float sm[8][33];
    sm[threadIdx.y][threadIdx.x] = acc;
    __syncthreads();
    if (threadIdx.y == 0) {
        float s = 0.f;
        #pragma unroll
        for (int r = 0; r < 8; r++) s += sm[r][threadIdx.x];
        g_t[b*NDIM + j] = BW / s;
    }
}

__global__ void pupdate_kernel() {
    int idx = blockIdx.x*256 + threadIdx.x;
    if (idx >= BATCH*MN) return;
    int b = idx / MN;
    int r = idx - b*MN;
    int i = r / NDIM;
    int j = r - i*NDIM;
    g_P[idx] = g_s[b*MDIM + i] * g_Km[idx] * g_t[b*NDIM + j];
}

__global__ void zeroacc_kernel() {
    if (threadIdx.x < BATCH*4) g_acc[threadIdx.x] = 0.f;
}

// block 0/2: t1c_b = sum_i rm*t1 ; block 1/3: t2c_b = sum_j cm*t2
__global__ void costdot_kernel() {
    int b = blockIdx.x >> 1;
    int which = blockIdx.x & 1;
    const float *x, *y; int len;
    if (which == 0) { x = g_rm + b*MDIM; y = g_t1 + b*MDIM; len = MDIM; }
    else            { x = g_cm + b*NDIM; y = g_t2 + b*NDIM; len = NDIM; }
    float s = 0.f;
    for (int k = threadIdx.x; k < len; k += 256) s += x[k]*y[k];
    __shared__ float red[256];
    red[threadIdx.x] = s;
    __syncthreads();
    for (int st = 128; st; st >>= 1) {
        if (threadIdx.x < st) red[threadIdx.x] += red[threadIdx.x + st];
        __syncthreads();
    }
    if (!threadIdx.x) g_acc[b*4 + which] = red[0];
}

__global__ void finish_kernel(float* out) {
    int b = threadIdx.x;
    if (b < BATCH)
        out[b] = g_acc[b*4+0] + g_acc[b*4+1] - 2.0f*g_acc[b*4+2];
}

__global__ void copyP_kernel(float* out) {
    int idx = blockIdx.x*256 + threadIdx.x;
    if (idx < BATCH*MN) out[2 + idx] = g_P[idx];
}

// ---------------- tiled GEMM (64x64 tile, 256 threads, 4x4 microtile) ------
// MODE 0: g_T = g_P @ D2        (Dp = D2; K = NDIM)
// MODE 1: g_Km = exp((2*(D1@g_T) - t1 - t2) * EPS_INV)   (Dp = D1; K = MDIM)
// MODE 2: cross += sum( (D1@g_P) .* g_T )                (Dp = D1; K = MDIM)
template<int MODE>
__global__ void __launch_bounds__(256) gemm_kernel(const float* __restrict__ Dp) {
    constexpr int Kdim = (MODE == 0) ? NDIM : MDIM;
    int b = blockIdx.z;
    const float* A;
    const float* Bm;
    if (MODE == 0) { A = g_P  + (long)b*MN;          Bm = Dp  + (long)b*NDIM*NDIM; }
    if (MODE == 1) { A = Dp   + (long)b*MDIM*MDIM;   Bm = g_T + (long)b*MN; }
    if (MODE == 2) { A = Dp   + (long)b*MDIM*MDIM;   Bm = g_P + (long)b*MN; }

    int row0 = blockIdx.y*64, col0 = blockIdx.x*64;
    __shared__ float As[16][64];
    __shared__ float Bs[16][64];
    int tid = threadIdx.x;
    int tx = tid & 15, ty = tid >> 4;
    int arow = tid >> 2, akq = tid & 3;   // A tile: 64 rows x 16 k, float4 per thread
    int brow = tid >> 4, bcq = tid & 15;  // B tile: 16 k x 64 cols, float4 per thread
    float c[4][4] = {};

    for (int k0 = 0; k0 < Kdim; k0 += 16) {
        float4 av = *(const float4*)(A  + (long)(row0 + arow)*Kdim + k0 + akq*4);
        float4 bv = *(const float4*)(Bm + (long)(k0 + brow)*NDIM + col0 + bcq*4);
        __syncthreads();
        As[akq*4+0][arow] = av.x;
        As[akq*4+1][arow] = av.y;
        As[akq*4+2][arow] = av.z;
        As[akq*4+3][arow] = av.w;
        *(float4*)&Bs[brow][bcq*4] = bv;
        __syncthreads();
        #pragma unroll
        for (int k = 0; k < 16; k++) {
            float4 a4 = *(const float4*)&As[k][ty*4];
            float4 b4 = *(const float4*)&Bs[k][tx*4];
            float ar[4] = {a4.x, a4.y, a4.z, a4.w};
            float br[4] = {b4.x, b4.y, b4.z, b4.w};
            #pragma unroll
            for (int i = 0; i < 4; i++)
                #pragma unroll
                for (int j = 0; j < 4; j++)
                    c[i][j] += ar[i]*br[j];
        }
    }

    if (MODE == 0) {
        float* Cb = g_T + (long)b*MN;
        #pragma unroll
        for (int i = 0; i < 4; i++) {
            int row = row0 + ty*4 + i;
            float4 v = make_float4(c[i][0], c[i][1], c[i][2], c[i][3]);
            *(float4*)(Cb + (long)row*NDIM + col0 + tx*4) = v;
        }
    } else if (MODE == 1) {
        float* Cb = g_Km + (long)b*MN;
        const float* t1b = g_t1 + b*MDIM;
        const float* t2b = g_t2 + b*NDIM;
        #pragma unroll
        for (int i = 0; i < 4; i++) {
            int row = row0 + ty*4 + i;
            float t1v = t1b[row];
            float4 v;
            float* vp = &v.x;
            #pragma unroll
            for (int j = 0; j < 4; j++) {
                int col = col0 + tx*4 + j;
                vp[j] = expf((2.0f*c[i][j] - t1v - t2b[col]) * EPS_INV);
            }
            *(float4*)(Cb + (long)row*NDIM + col0 + tx*4) = v;
        }
    } else {
        const float* Tb = g_T + (long)b*MN;
        float local = 0.f;
        #pragma unroll
        for (int i = 0; i < 4; i++) {
            int row = row0 + ty*4 + i;
            #pragma unroll
            for (int j = 0; j < 4; j++)
                local += c[i][j] * Tb[(long)row*NDIM + col0 + tx*4 + j];
        }
        __shared__ float red[256];
        red[tid] = local;
        __syncthreads();
        for (int st = 128; st; st >>= 1) {
            if (tid < st) red[tid] += red[tid + st];
            __syncthreads();
        }
        if (!tid) atomicAdd(&g_acc[b*4 + 2], red[0]);
    }
}

// ---------------- host driver ----------------
extern "C" void kernel_launch(void* const* d_in, const int* in_sizes, int n_in,
                              void* d_out, int out_size) {
    const float* D1 = (const float*)d_in[0];
    const float* D2 = (const float*)d_in[1];
    if (n_in >= 2 && in_sizes[0] == BATCH*NDIM*NDIM && in_sizes[1] == BATCH*MDIM*MDIM) {
        const float* tmp = D1; D1 = D2; D2 = tmp;   // defensive: order by size
    }
    float* out = (float*)d_out;

    dim3 gemm_grid(NDIM/64, MDIM/64, BATCH);   // (8, 12, 2)
    dim3 col_grid(NDIM/32, BATCH);             // (16, 2)
    dim3 col_blk(32, 8);

    pinit_kernel<<<(BATCH*MN + 255)/256, 256>>>();

    for (int o = 0; o < 10; o++) {
        rowsumP_kernel<<<192, 256>>>();            // 1536 warps
        colsumP_kernel<<<col_grid, col_blk>>>();
        sqmv_kernel<0><<<192, 256>>>(D1);          // 1536 warps
        sqmv_kernel<1><<<128, 256>>>(D2);          // 1024 warps
        vinit_kernel<<<4, 256>>>();
        gemm_kernel<0><<<gemm_grid, 256>>>(D2);    // T = P @ D2
        gemm_kernel<1><<<gemm_grid, 256>>>(D1);    // K = exp(-(G)/eps), G via D1@T
        for (int it = 0; it < 20; it++) {
            uupdate_kernel<<<192, 256>>>();
            vupdate_kernel<<<col_grid, col_blk>>>();
        }
        pupdate_kernel<<<(BATCH*MN + 255)/256, 256>>>();
    }

    // final cost
    rowsumP_kernel<<<192, 256>>>();
    colsumP_kernel<<<col_grid, col_blk>>>();
    sqmv_kernel<0><<<192, 256>>>(D1);
    sqmv_kernel<1><<<128, 256>>>(D2);
    zeroacc_kernel<<<1, 32>>>();
    costdot_kernel<<<4, 256>>>();
    gemm_kernel<0><<<gemm_grid, 256>>>(D2);        // T = P @ D2 (final P)
    gemm_kernel<2><<<gemm_grid, 256>>>(D1);        // cross = sum((D1@P) .* T)

    if (out_size >= 2)
        finish_kernel<<<1, 32>>>(out);
    if (out_size >= 2 + BATCH*MN)
        copyP_kernel<<<(BATCH*MN + 255)/256, 256>>>(out);
}

// round 2
// speedup vs baseline: 2.0400x; 2.0400x over previous
#include <cuda_runtime.h>
#include <cuda_bf16.h>

#define NBLK 256
#define NTHR 256
#define B_ 2
#define M_ 768
#define N_ 512
#define MN_ (M_*N_)
#define AW (1.0f/768.0f)
#define BW (1.0f/512.0f)
#define EPSI 20.0f
#define RPB 6      // rows per block (B*M / NBLK)
#define BPB 128    // blocks per batch

// ---------------- device scratch ----------------
__device__ float g_P [B_*MN_];
__device__ float g_Km[B_*MN_];
__device__ float g_T [B_*MN_];
__device__ float g_rm[B_*M_];
__device__ float g_t1[B_*M_];
__device__ float g_t2[B_*N_];
__device__ float g_t [B_*N_];
__device__ float g_part[B_*BPB*N_];
__device__ float g_cp[192];
__device__ float g_acc[4];
__device__ unsigned g_arrive;
__device__ unsigned g_release;

__global__ void reset_kernel() { g_arrive = 0u; g_release = 0u; }

// ---------------- grid barrier (all blocks resident) ----------------
__device__ __forceinline__ void gsync(unsigned target) {
    __syncthreads();
    if (threadIdx.x == 0) {
        __threadfence();
        unsigned old = atomicAdd(&g_arrive, 1u);
        if (old == NBLK - 1u) {
            g_arrive = 0u;
            __threadfence();
            atomicExch(&g_release, target);
        } else {
            unsigned v;
            do {
                asm volatile("ld.acquire.gpu.b32 %0, [%1];" : "=r"(v) : "l"(&g_release));
                if (v >= target) break;
                __nanosleep(32);
            } while (true);
        }
    }
    __syncthreads();
}

// ---------------- GEMM tile (64x64, 4x4 micro) ----------------
// MODE 0: g_T = g_P @ D2         (A=g_P lda=512, B=D2 ldb=512, K=512)
// MODE 1: g_Km = exp((2*(D1@g_T) - t1 - t2)*EPSI)  (A=D1 lda=768, B=g_T, K=768)
// MODE 2: g_cp[tile] = sum((D1@g_P)_tile .* g_T_tile)
template<int MODE>
__device__ void gemm_tile(int tile, const float* __restrict__ Aroot,
                          const float* __restrict__ Broot,
                          float* As, float* Bs, float* red) {
    const int Kd = (MODE == 0) ? N_ : M_;
    int b = tile / 96;
    int r = tile - b * 96;
    int row0 = (r >> 3) * 64, col0 = (r & 7) * 64;
    const float* A  = Aroot + (size_t)b * ((MODE == 0) ? MN_ : M_*M_);
    const float* Bm = Broot + (size_t)b * ((MODE == 0) ? (size_t)N_*N_ : MN_);

    int tid = threadIdx.x;
    int tx = tid & 15, ty = tid >> 4;
    int arow = tid >> 2, akq = tid & 3;
    int brow = tid >> 4, bcq = tid & 15;
    float c[4][4] = {};

    for (int k0 = 0; k0 < Kd; k0 += 16) {
        float4 av = *(const float4*)(A  + (size_t)(row0 + arow)*Kd + k0 + akq*4);
        float4 bv = *(const float4*)(Bm + (size_t)(k0 + brow)*N_ + col0 + bcq*4);
        __syncthreads();
        As[(akq*4+0)*64 + arow] = av.x;
        As[(akq*4+1)*64 + arow] = av.y;
        As[(akq*4+2)*64 + arow] = av.z;
        As[(akq*4+3)*64 + arow] = av.w;
        *(float4*)&Bs[brow*64 + bcq*4] = bv;
        __syncthreads();
        #pragma unroll
        for (int k = 0; k < 16; k++) {
            float4 a4 = *(const float4*)&As[k*64 + ty*4];
            float4 b4 = *(const float4*)&Bs[k*64 + tx*4];
            float ar[4] = {a4.x, a4.y, a4.z, a4.w};
            float br[4] = {b4.x, b4.y, b4.z, b4.w};
            #pragma unroll
            for (int i = 0; i < 4; i++)
                #pragma unroll
                for (int j = 0; j < 4; j++)
                    c[i][j] += ar[i]*br[j];
        }
    }

    if (MODE == 0) {
        float* Cb = g_T + (size_t)b*MN_;
        #pragma unroll
        for (int i = 0; i < 4; i++) {
            int row = row0 + ty*4 + i;
            float4 v = make_float4(c[i][0], c[i][1], c[i][2], c[i][3]);
            *(float4*)(Cb + (size_t)row*N_ + col0 + tx*4) = v;
        }
    } else if (MODE == 1) {
        float* Cb = g_Km + (size_t)b*MN_;
        const float* t1b = g_t1 + b*M_;
        const float* t2b = g_t2 + b*N_;
        #pragma unroll
        for (int i = 0; i < 4; i++) {
            int row = row0 + ty*4 + i;
            float t1v = t1b[row];
            float4 v;
            float* vp = &v.x;
            #pragma unroll
            for (int j = 0; j < 4; j++) {
                int col = col0 + tx*4 + j;
                vp[j] = __expf((2.0f*c[i][j] - t1v - t2b[col]) * EPSI);
            }
            *(float4*)(Cb + (size_t)row*N_ + col0 + tx*4) = v;
        }
    } else {
        const float* Tb = g_T + (size_t)b*MN_;
        float local = 0.f;
        #pragma unroll
        for (int i = 0; i < 4; i++) {
            int row = row0 + ty*4 + i;
            #pragma unroll
            for (int j = 0; j < 4; j++)
                local += c[i][j] * Tb[(size_t)row*N_ + col0 + tx*4 + j];
        }
        red[tid] = local;
        __syncthreads();
        for (int st = 128; st; st >>= 1) {
            if (tid < st) red[tid] += red[tid + st];
            __syncthreads();
        }
        if (!tid) g_cp[tile] = red[0];
    }
}

// ---------------- t1 = (D1.^2) @ rm  (blocks 192..255, warp per row) -------
__device__ void sqmv_t1(const float* __restrict__ D1, int bid, int wid, int lane) {
    int gwarp = (bid - 192)*8 + wid;   // 0..511
    #pragma unroll
    for (int k = 0; k < 3; k++) {
        int fi = gwarp + k*512;        // 0..1535
        int b2 = fi / M_;
        int i  = fi - b2*M_;
        const float* row = D1 + ((size_t)b2*M_ + i)*M_;
        const float* rmb = g_rm + b2*M_;
        float s = 0.f;
        for (int kk = lane; kk < M_; kk += 32) { float v = row[kk]; s += v*v*rmb[kk]; }
        #pragma unroll
        for (int o = 16; o; o >>= 1) s += __shfl_xor_sync(0xffffffffu, s, o);
        if (!lane) g_t1[fi] = s;
    }
}

// ---------------- persistent mega-kernel ----------------
__global__ void __launch_bounds__(NTHR, 2)
gw_kernel(const float* __restrict__ D1, const float* __restrict__ D2,
          float* __restrict__ out, int out_size) {
    int bid = blockIdx.x, tid = threadIdx.x;
    int wid = tid >> 5, lane = tid & 31;
    unsigned gen = 0;

    __shared__ float sKs[RPB*N_];     // 3072 floats; aliased as As/Bs during GEMM
    __shared__ float sRed[272];
    float* As = sKs;
    float* Bs = sKs + 1024;
    float* s_local = sRed + 260;      // 6 floats

    int bb = bid >> 7;                         // batch of my rows
    size_t rowbase = (size_t)bid * (RPB*N_);   // offset into flat [B*M,N] arrays

    // ---------- Phase I: init P, rm, t2 ----------
    for (int idx = tid; idx < RPB*N_; idx += NTHR) g_P[rowbase + idx] = AW*BW;
    { int i = bid*NTHR + tid; if (i < B_*M_) g_rm[i] = AW; }
    {
        int gw = bid*8 + wid;
        if (gw < B_*N_) {
            int b2 = gw >> 9, j = gw & 511;
            const float* row = D2 + ((size_t)b2*N_ + j)*N_;
            float s = 0.f;
            for (int l = lane; l < N_; l += 32) { float v = row[l]; s += v*v; }
            #pragma unroll
            for (int o = 16; o; o >>= 1) s += __shfl_xor_sync(0xffffffffu, s, o);
            if (!lane) g_t2[gw] = BW * s;
        }
    }
    gsync(++gen);

    // ---------- 10 outer iterations ----------
    for (int outer = 0; outer < 10; outer++) {
        // Phase A: gemm0 (T = P@D2) on blocks 0..191; t1 sqmv on 192..255
        if (bid < 192) gemm_tile<0>(bid, g_P, D2, As, Bs, sRed);
        else           sqmv_t1(D1, bid, wid, lane);
        gsync(++gen);

        // Phase B: gemm1 (Km = exp(...))
        if (bid < 192) gemm_tile<1>(bid, D1, g_T, As, Bs, sRed);
        gsync(++gen);

        // Sinkhorn: 20 iterations, K cached in SMEM
        for (int it = 0; it < 20; it++) {
            // --- U phase: s for own rows + column partials ---
            if (it == 0) {
                for (int idx = tid; idx < RPB*N_; idx += NTHR)
                    sKs[idx] = g_Km[rowbase + idx];
            }
            __syncthreads();
            if (wid < RPB) {
                const float* tb = g_t + bb*N_;
                float s = 0.f;
                if (it == 0) {
                    for (int j = lane; j < N_; j += 32) s += sKs[wid*N_ + j];
                } else {
                    for (int j = lane; j < N_; j += 32) s += sKs[wid*N_ + j] * tb[j];
                }
                #pragma unroll
                for (int o = 16; o; o >>= 1) s += __shfl_xor_sync(0xffffffffu, s, o);
                if (!lane) s_local[wid] = __fdividef(AW, s);
            }
            __syncthreads();
            {
                float a0 = 0.f, a1 = 0.f;
                #pragma unroll
                for (int rr = 0; rr < RPB; rr++) {
                    float sv = s_local[rr];
                    a0 += sKs[rr*N_ + tid]       * sv;
                    a1 += sKs[rr*N_ + tid + 256] * sv;
                }
                float* pb = g_part + ((size_t)bb*BPB + (bid & 127))*N_;
                pb[tid]       = a0;
                pb[tid + 256] = a1;
            }
            gsync(++gen);

            // --- V phase: t[j] = BW / sum_c part[c][j]  (blocks 0..31) ---
            if (bid < 32) {
                int e  = bid*32 + lane;       // t-entry 0..1023
                int cg = wid;                 // 0..7 -> 16 contributors each
                int b2 = e >> 9, j = e & 511;
                const float* pp = g_part + ((size_t)b2*BPB + cg*16)*N_ + j;
                float s = 0.f;
                #pragma unroll
                for (int c = 0; c < 16; c++) s += pp[(size_t)c*N_];
                sRed[tid] = s;
                __syncthreads();
                if (cg == 0) {
                    float tot = 0.f;
                    #pragma unroll
                    for (int g2 = 0; g2 < 8; g2++) tot += sRed[g2*32 + lane];
                    g_t[e] = __fdividef(BW, tot);
                }
            }
            gsync(++gen);
        }

        // Phase D: P = s*K*t, rm = rowsum(P)
        {
            const float* tb = g_t + bb*N_;
            if (wid < RPB) {
                float s = 0.f;
                for (int j = lane; j < N_; j += 32) s += sKs[wid*N_ + j] * tb[j];
                #pragma unroll
                for (int o = 16; o; o >>= 1) s += __shfl_xor_sync(0xffffffffu, s, o);
                if (!lane) g_rm[bid*RPB + wid] = s_local[wid] * s;
            }
            #pragma unroll
            for (int rr = 0; rr < RPB; rr++) {
                float sv = s_local[rr];
                g_P[rowbase + rr*N_ + tid]       = sv * sKs[rr*N_ + tid]       * tb[tid];
                g_P[rowbase + rr*N_ + tid + 256] = sv * sKs[rr*N_ + tid + 256] * tb[tid + 256];
            }
        }
        gsync(++gen);
    }

    // ---------- Final cost ----------
    // F1: T = P@D2 (final P) + t1 with final rm
    if (bid < 192) gemm_tile<0>(bid, g_P, D2, As, Bs, sRed);
    else           sqmv_t1(D1, bid, wid, lane);
    gsync(++gen);

    // F2: cross partials + t1c/t2c dots
    if (bid < 192) {
        gemm_tile<2>(bid, D1, g_P, As, Bs, sRed);
    } else if (bid == 255) {
        for (int b2 = 0; b2 < 2; b2++) {
            float s = 0.f;
            for (int i = tid; i < M_; i += NTHR) s += g_rm[b2*M_ + i] * g_t1[b2*M_ + i];
            sRed[tid] = s;
            __syncthreads();
            for (int st = 128; st; st >>= 1) {
                if (tid < st) sRed[tid] += sRed[tid + st];
                __syncthreads();
            }
            if (!tid) g_acc[b2] = sRed[0];
            __syncthreads();
        }
    } else if (bid == 254) {
        for (int b2 = 0; b2 < 2; b2++) {
            float s = 0.f;
            for (int j = tid; j < N_; j += NTHR) s += g_t2[b2*N_ + j];
            sRed[tid] = s;
            __syncthreads();
            for (int st = 128; st; st >>= 1) {
                if (tid < st) sRed[tid] += sRed[tid + st];
                __syncthreads();
            }
            if (!tid) g_acc[2 + b2] = BW * sRed[0];
            __syncthreads();
        }
    }
    gsync(++gen);

    // F3: final scalar outputs + copy P
    if (bid == 0 && tid < 2) {
        float cr = 0.f;
        for (int tl = 0; tl < 96; tl++) cr += g_cp[tid*96 + tl];
        out[tid] = g_acc[tid] + g_acc[2 + tid] - 2.0f * cr;
    }
    if (out_size > 2) {
        for (int idx = tid; idx < RPB*N_; idx += NTHR)
            out[2 + rowbase + idx] = g_P[rowbase + idx];
    }
}

// ---------------- host driver ----------------
extern "C" void kernel_launch(void* const* d_in, const int* in_sizes, int n_in,
                              void* d_out, int out_size) {
    const float* D1 = (const float*)d_in[0];
    const float* D2 = (const float*)d_in[1];
    if (n_in >= 2 && in_sizes[0] == B_*N_*N_ && in_sizes[1] == B_*M_*M_) {
        const float* tmp = D1; D1 = D2; D2 = tmp;
    }
    float* out = (float*)d_out;

    reset_kernel<<<1, 1>>>();
    gw_kernel<<<NBLK, NTHR>>>(D1, D2, out, out_size);
}

// round 3
// speedup vs baseline: 2.6631x; 1.3055x over previous
#include <cuda_runtime.h>

#define NBLK 128
#define NTHR 256
#define B_ 2
#define M_ 768
#define N_ 512
#define MN_ (M_*N_)
#define AW (1.0f/768.0f)
#define BW (1.0f/512.0f)
#define EPSI 20.0f
#define RPB 12     // rows per block: 128*12 = 1536 = B*M

typedef unsigned long long ull;

// ---------------- device scratch ----------------
__device__ float g_P [B_*MN_];
__device__ float g_Km[B_*MN_];
__device__ float g_T [B_*MN_];
__device__ float g_rm[B_*M_];
__device__ float g_t1[B_*M_];
__device__ float g_t2[B_*N_];
__device__ float g_csum[3][B_*N_];   // triple-buffered atomic column sums
__device__ float g_cp[96];
__device__ float g_acc[4];
__device__ unsigned g_arrive, g_release;

__global__ void reset_kernel() { g_arrive = 0u; g_release = 0u; }

// ---------------- grid barrier (128 blocks, all resident) ----------------
__device__ __forceinline__ void gsync(unsigned &gen) {
    ++gen;
    __syncthreads();
    if (threadIdx.x == 0) {
        __threadfence();
        unsigned old = atomicAdd(&g_arrive, 1u);
        if (old == NBLK - 1u) {
            g_arrive = 0u;
            __threadfence();
            atomicExch(&g_release, gen);
        } else {
            unsigned v;
            do {
                asm volatile("ld.acquire.gpu.b32 %0, [%1];" : "=r"(v) : "l"(&g_release));
                if (v >= gen) break;
                __nanosleep(16);
            } while (true);
        }
    }
    __syncthreads();
}

// ---------------- packed f32x2 helpers ----------------
__device__ __forceinline__ void fma2(ull &d, ull a, ull b) {
    asm("fma.rn.f32x2 %0, %1, %2, %0;" : "+l"(d) : "l"(a), "l"(b));
}
__device__ __forceinline__ ull splat(float x) {
    ull r; asm("mov.b64 %0, {%1, %1};" : "=l"(r) : "f"(x)); return r;
}

// ---------------- GEMM tile 128x64, micro 8x4 via f32x2 ----------------
// MODE 0: g_T  = g_P @ D2                         (A=P lda=512, B=D2, K=512)
// MODE 1: g_Km = exp((2*(D1@g_T) - t1 - t2)*EPSI) (A=D1 lda=768, B=T,  K=768)
// MODE 2: g_cp[tile] = sum((D1@g_P)_tile .* g_T_tile)
template<int MODE>
__device__ void gemm_tile(int tile, const float* __restrict__ D1,
                          const float* __restrict__ D2,
                          float* As, float* Bs, float* red) {
    const int Kd  = (MODE == 0) ? N_ : M_;
    const int lda = (MODE == 0) ? N_ : M_;
    int b = tile / 48;
    int r = tile - b*48;
    int row0 = (r >> 3) * 128;
    int col0 = (r & 7) * 64;
    const float* A  = (MODE == 0) ? (g_P + (size_t)b*MN_) : (D1 + (size_t)b*M_*M_);
    const float* Bm = (MODE == 0) ? (D2 + (size_t)b*(size_t)N_*N_)
                    : (MODE == 1) ? (g_T + (size_t)b*MN_)
                                  : (g_P + (size_t)b*MN_);

    int tid = threadIdx.x;
    int arow = tid >> 1, ah = (tid & 1) * 8;
    int brow = tid >> 4, bq = tid & 15;
    int tx = tid & 15, ty = tid >> 4;

    ull acc[4][4];
    #pragma unroll
    for (int i = 0; i < 4; i++)
        #pragma unroll
        for (int j = 0; j < 4; j++) acc[i][j] = 0ull;

    const float* Ar = A + (size_t)(row0 + arow)*lda + ah;
    const float* Br = Bm + (size_t)brow*N_ + col0 + bq*4;

    for (int k0 = 0; k0 < Kd; k0 += 16) {
        float4 a0 = *(const float4*)(Ar + k0);
        float4 a1 = *(const float4*)(Ar + k0 + 4);
        float4 bv = *(const float4*)(Br + (size_t)k0*N_);
        __syncthreads();
        As[(ah+0)*128 + arow] = a0.x;
        As[(ah+1)*128 + arow] = a0.y;
        As[(ah+2)*128 + arow] = a0.z;
        As[(ah+3)*128 + arow] = a0.w;
        As[(ah+4)*128 + arow] = a1.x;
        As[(ah+5)*128 + arow] = a1.y;
        As[(ah+6)*128 + arow] = a1.z;
        As[(ah+7)*128 + arow] = a1.w;
        *(float4*)&Bs[brow*64 + bq*4] = bv;
        __syncthreads();
        #pragma unroll
        for (int k = 0; k < 16; k++) {
            ulonglong2 ua0 = *(const ulonglong2*)&As[k*128 + ty*8];
            ulonglong2 ua1 = *(const ulonglong2*)&As[k*128 + ty*8 + 4];
            float4 b4 = *(const float4*)&Bs[k*64 + tx*4];
            ull bp0 = splat(b4.x), bp1 = splat(b4.y), bp2 = splat(b4.z), bp3 = splat(b4.w);
            fma2(acc[0][0], ua0.x, bp0); fma2(acc[0][1], ua0.x, bp1);
            fma2(acc[0][2], ua0.x, bp2); fma2(acc[0][3], ua0.x, bp3);
            fma2(acc[1][0], ua0.y, bp0); fma2(acc[1][1], ua0.y, bp1);
            fma2(acc[1][2], ua0.y, bp2); fma2(acc[1][3], ua0.y, bp3);
            fma2(acc[2][0], ua1.x, bp0); fma2(acc[2][1], ua1.x, bp1);
            fma2(acc[2][2], ua1.x, bp2); fma2(acc[2][3], ua1.x, bp3);
            fma2(acc[3][0], ua1.y, bp0); fma2(acc[3][1], ua1.y, bp1);
            fma2(acc[3][2], ua1.y, bp2); fma2(acc[3][3], ua1.y, bp3);
        }
    }

    float cS[8][4];
    #pragma unroll
    for (int rp = 0; rp < 4; rp++)
        #pragma unroll
        for (int j = 0; j < 4; j++) {
            union { ull u; float f[2]; } cv; cv.u = acc[rp][j];
            cS[2*rp][j]   = cv.f[0];
            cS[2*rp+1][j] = cv.f[1];
        }

    if (MODE == 0) {
        float* Cb = g_T + (size_t)b*MN_;
        #pragma unroll
        for (int rr = 0; rr < 8; rr++) {
            int row = row0 + ty*8 + rr;
            float4 v = make_float4(cS[rr][0], cS[rr][1], cS[rr][2], cS[rr][3]);
            *(float4*)(Cb + (size_t)row*N_ + col0 + tx*4) = v;
        }
    } else if (MODE == 1) {
        float* Cb = g_Km + (size_t)b*MN_;
        const float* t1b = g_t1 + b*M_;
        const float* t2b = g_t2 + b*N_;
        #pragma unroll
        for (int rr = 0; rr < 8; rr++) {
            int row = row0 + ty*8 + rr;
            float t1v = t1b[row];
            float4 v;
            v.x = __expf((2.0f*cS[rr][0] - t1v - t2b[col0+tx*4+0]) * EPSI);
            v.y = __expf((2.0f*cS[rr][1] - t1v - t2b[col0+tx*4+1]) * EPSI);
            v.z = __expf((2.0f*cS[rr][2] - t1v - t2b[col0+tx*4+2]) * EPSI);
            v.w = __expf((2.0f*cS[rr][3] - t1v - t2b[col0+tx*4+3]) * EPSI);
            *(float4*)(Cb + (size_t)row*N_ + col0 + tx*4) = v;
        }
    } else {
        const float* Tb = g_T + (size_t)b*MN_;
        float local = 0.f;
        #pragma unroll
        for (int rr = 0; rr < 8; rr++) {
            int row = row0 + ty*8 + rr;
            float4 tv = *(const float4*)(Tb + (size_t)row*N_ + col0 + tx*4);
            local += cS[rr][0]*tv.x + cS[rr][1]*tv.y + cS[rr][2]*tv.z + cS[rr][3]*tv.w;
        }
        red[tid] = local;
        __syncthreads();
        for (int st = 128; st; st >>= 1) {
            if (tid < st) red[tid] += red[tid + st];
            __syncthreads();
        }
        if (!tid) g_cp[tile] = red[0];
    }
}

// ---------------- t1 = (D1.^2) @ rm  (blocks 96..127) ----------------
__device__ void sqmv_t1(const float* __restrict__ D1, int bid, int wid, int lane) {
    int gw = (bid - 96)*8 + wid;   // 0..255
    #pragma unroll
    for (int k = 0; k < 6; k++) {
        int fi = gw + k*256;       // 0..1535
        int b2 = fi >= M_;
        int i  = fi - b2*M_;
        const float4* row = (const float4*)(D1 + ((size_t)b2*M_ + i)*M_);
        const float* rmb = g_rm + b2*M_;
        float s = 0.f;
        for (int q = lane; q < 192; q += 32) {
            float4 v  = row[q];
            float4 r4 = *(const float4*)&rmb[q*4];
            s += v.x*v.x*r4.x + v.y*v.y*r4.y + v.z*v.z*r4.z + v.w*v.w*r4.w;
        }
        #pragma unroll
        for (int o = 16; o; o >>= 1) s += __shfl_xor_sync(0xffffffffu, s, o);
        if (!lane) g_t1[fi] = s;
    }
}

// ---------------- persistent mega-kernel ----------------
__global__ void __launch_bounds__(NTHR)
gw_kernel(const float* __restrict__ D1, const float* __restrict__ D2,
          float* __restrict__ out, int out_size) {
    __shared__ float sKs[RPB*N_];   // 24 KB K-row cache
    __shared__ float As[16*128];    // 8 KB
    __shared__ float Bs[16*64];     // 4 KB
    __shared__ float tS[N_];        // 2 KB
    __shared__ float sRed[NTHR];
    __shared__ float sLoc[RPB];

    int bid = blockIdx.x, tid = threadIdx.x;
    int wid = tid >> 5, lane = tid & 31;
    unsigned gen = 0;
    int bb = bid >> 6;                          // batch (64 blocks each)
    size_t rowbase = (size_t)bid * (RPB*N_);

    // ---------- Phase I: init P, rm, t2, csum[0] ----------
    for (int idx = tid; idx < RPB*N_; idx += NTHR) g_P[rowbase + idx] = AW*BW;
    if (tid < RPB) g_rm[bid*RPB + tid] = AW;
    {
        int gw2 = bid*8 + wid;                  // 0..1023
        int b2 = gw2 >> 9, j = gw2 & 511;
        const float4* row = (const float4*)(D2 + ((size_t)b2*N_ + j)*N_);
        float s = 0.f;
        for (int q = lane; q < 128; q += 32) {
            float4 v = row[q];
            s += v.x*v.x + v.y*v.y + v.z*v.z + v.w*v.w;
        }
        #pragma unroll
        for (int o = 16; o; o >>= 1) s += __shfl_xor_sync(0xffffffffu, s, o);
        if (!lane) g_t2[gw2] = BW * s;
    }
    if (bid == 0)
        for (int idx = tid; idx < B_*N_; idx += NTHR) g_csum[0][idx] = 0.f;
    gsync(gen);

    int git = 0;
    for (int outer = 0; outer < 10; outer++) {
        // Phase A: T = P@D2 (96 blocks) || t1 sqmv (32 blocks)
        if (bid < 96) gemm_tile<0>(bid, D1, D2, As, Bs, sRed);
        else          sqmv_t1(D1, bid, wid, lane);
        gsync(gen);

        // Phase B: Km = exp(...)
        if (bid < 96) gemm_tile<1>(bid, D1, D2, As, Bs, sRed);
        gsync(gen);

        // Sinkhorn: 20 iterations, 1 barrier each
        for (int it = 0; it < 20; it++, git++) {
            if (it == 0) {
                const float4* src = (const float4*)(g_Km + rowbase);
                float4* dst = (float4*)sKs;
                for (int idx = tid; idx < RPB*N_/4; idx += NTHR) dst[idx] = src[idx];
                __syncthreads();
            }
            // u-dots: rows 0..7 (all warps), rows 8..11 (warps 0..3)
            {
                int r = wid;
                float s = 0.f;
                if (it == 0) {
                    for (int q = lane; q < 128; q += 32) {
                        float4 v = *(const float4*)&sKs[r*N_ + q*4];
                        s += v.x + v.y + v.z + v.w;
                    }
                } else {
                    for (int q = lane; q < 128; q += 32) {
                        float4 v  = *(const float4*)&sKs[r*N_ + q*4];
                        float4 t4 = *(const float4*)&tS[q*4];
                        s += v.x*t4.x + v.y*t4.y + v.z*t4.z + v.w*t4.w;
                    }
                }
                #pragma unroll
                for (int o = 16; o; o >>= 1) s += __shfl_xor_sync(0xffffffffu, s, o);
                if (!lane) sLoc[r] = __fdividef(AW, s);
            }
            if (wid < 4) {
                int r = 8 + wid;
                float s = 0.f;
                if (it == 0) {
                    for (int q = lane; q < 128; q += 32) {
                        float4 v = *(const float4*)&sKs[r*N_ + q*4];
                        s += v.x + v.y + v.z + v.w;
                    }
                } else {
                    for (int q = lane; q < 128; q += 32) {
                        float4 v  = *(const float4*)&sKs[r*N_ + q*4];
                        float4 t4 = *(const float4*)&tS[q*4];
                        s += v.x*t4.x + v.y*t4.y + v.z*t4.z + v.w*t4.w;
                    }
                }
                #pragma unroll
                for (int o = 16; o; o >>= 1) s += __shfl_xor_sync(0xffffffffu, s, o);
                if (!lane) sLoc[r] = __fdividef(AW, s);
            }
            __syncthreads();
            // column partials -> atomic accumulate; zero buffer for git+1
            {
                float a0 = 0.f, a1 = 0.f;
                #pragma unroll
                for (int rr = 0; rr < RPB; rr++) {
                    float sv = sLoc[rr];
                    a0 += sKs[rr*N_ + tid]       * sv;
                    a1 += sKs[rr*N_ + tid + 256] * sv;
                }
                int p = git % 3;
                atomicAdd(&g_csum[p][bb*N_ + tid],       a0);
                atomicAdd(&g_csum[p][bb*N_ + tid + 256], a1);
                int pn = (p + 1 == 3) ? 0 : p + 1;
                if (tid < 8) g_csum[pn][bb*N_ + (bid & 63)*8 + tid] = 0.f;
            }
            gsync(gen);
            // t recompute (redundant per block, into SMEM)
            {
                int p = git % 3;
                tS[tid]       = __fdividef(BW, g_csum[p][bb*N_ + tid]);
                tS[tid + 256] = __fdividef(BW, g_csum[p][bb*N_ + tid + 256]);
            }
            __syncthreads();
        }

        // P update + row masses
        {
            int r = wid;
            float s = 0.f;
            for (int q = lane; q < 128; q += 32) {
                float4 v  = *(const float4*)&sKs[r*N_ + q*4];
                float4 t4 = *(const float4*)&tS[q*4];
                s += v.x*t4.x + v.y*t4.y + v.z*t4.z + v.w*t4.w;
            }
            #pragma unroll
            for (int o = 16; o; o >>= 1) s += __shfl_xor_sync(0xffffffffu, s, o);
            if (!lane) g_rm[bid*RPB + r] = sLoc[r] * s;
        }
        if (wid < 4) {
            int r = 8 + wid;
            float s = 0.f;
            for (int q = lane; q < 128; q += 32) {
                float4 v  = *(const float4*)&sKs[r*N_ + q*4];
                float4 t4 = *(const float4*)&tS[q*4];
                s += v.x*t4.x + v.y*t4.y + v.z*t4.z + v.w*t4.w;
            }
            #pragma unroll
            for (int o = 16; o; o >>= 1) s += __shfl_xor_sync(0xffffffffu, s, o);
            if (!lane) g_rm[bid*RPB + r] = sLoc[r] * s;
        }
        #pragma unroll
        for (int rr = 0; rr < RPB; rr++) {
            float sv = sLoc[rr];
            g_P[rowbase + rr*N_ + tid]       = sv * sKs[rr*N_ + tid]       * tS[tid];
            g_P[rowbase + rr*N_ + tid + 256] = sv * sKs[rr*N_ + tid + 256] * tS[tid + 256];
        }
        gsync(gen);
    }

    // ---------- Final cost ----------
    // F1: T = P@D2 (final P) + t1 with final rm
    if (bid < 96) gemm_tile<0>(bid, D1, D2, As, Bs, sRed);
    else          sqmv_t1(D1, bid, wid, lane);
    gsync(gen);

    // F2: cross partials (96 blocks) + scalar dots (blocks 96, 97)
    if (bid < 96) {
        gemm_tile<2>(bid, D1, D2, As, Bs, sRed);
    } else if (bid == 96) {
        for (int b2 = 0; b2 < 2; b2++) {
            float s = 0.f;
            for (int i = tid; i < M_; i += NTHR) s += g_rm[b2*M_ + i] * g_t1[b2*M_ + i];
            sRed[tid] = s;
            __syncthreads();
            for (int st = 128; st; st >>= 1) {
                if (tid < st) sRed[tid] += sRed[tid + st];
                __syncthreads();
            }
            if (!tid) g_acc[b2] = sRed[0];
            __syncthreads();
        }
    } else if (bid == 97) {
        for (int b2 = 0; b2 < 2; b2++) {
            float s = 0.f;
            for (int j = tid; j < N_; j += NTHR) s += g_t2[b2*N_ + j];
            sRed[tid] = s;
            __syncthreads();
            for (int st = 128; st; st >>= 1) {
                if (tid < st) sRed[tid] += sRed[tid + st];
                __syncthreads();
            }
            if (!tid) g_acc[2 + b2] = BW * sRed[0];
            __syncthreads();
        }
    }
    gsync(gen);

    // F3: outputs
    if (bid == 0 && tid < 2) {
        float cr = 0.f;
        for (int t = 0; t < 48; t++) cr += g_cp[tid*48 + t];
        out[tid] = g_acc[tid] + g_acc[2 + tid] - 2.0f*cr;
    }
    if (out_size > 2) {
        const float2* src = (const float2*)(g_P + rowbase);
        float2* dst = (float2*)(out + 2 + rowbase);
        for (int idx = tid; idx < RPB*N_/2; idx += NTHR) dst[idx] = src[idx];
    }
}

// ---------------- host driver ----------------
extern "C" void kernel_launch(void* const* d_in, const int* in_sizes, int n_in,
                              void* d_out, int out_size) {
    const float* D1 = (const float*)d_in[0];
    const float* D2 = (const float*)d_in[1];
    if (n_in >= 2 && in_sizes[0] == B_*N_*N_ && in_sizes[1] == B_*M_*M_) {
        const float* tmp = D1; D1 = D2; D2 = tmp;
    }
    float* out = (float*)d_out;

    reset_kernel<<<1, 1>>>();
    gw_kernel<<<NBLK, NTHR>>>(D1, D2, out, out_size);
}

// round 4
// speedup vs baseline: 3.3489x; 1.2575x over previous
#include <cuda_runtime.h>

#define NBLK 128
#define NTHR 256
#define B_ 2
#define M_ 768
#define N_ 512
#define MN_ (M_*N_)
#define AW (1.0f/768.0f)
#define BW (1.0f/512.0f)
#define EPSI 20.0f
#define RPB 12            // rows per block: 128*12 = 1536 = B*M
#define AS_STRIDE 98      // padded (96+2) to avoid STS bank conflicts, keeps 8B align
#define AS_BUF (16*AS_STRIDE)
#define BS_BUF (16*64)

typedef unsigned long long ull;

// ---------------- device scratch ----------------
__device__ float g_P [B_*MN_];
__device__ float g_Km[B_*MN_];
__device__ float g_T [B_*MN_];
__device__ float g_rm[B_*M_];
__device__ float g_t1[B_*M_];
__device__ float g_t2[B_*N_];
__device__ float g_csum[3][B_*N_];   // triple-buffered atomic column sums
__device__ float g_cp[128];
__device__ float g_acc[4];
__device__ unsigned g_arrive, g_release;

__global__ void reset_kernel() { g_arrive = 0u; g_release = 0u; }

// ---------------- grid barrier: tight poll, no nanosleep ----------------
__device__ __forceinline__ void gsync(unsigned &gen) {
    ++gen;
    __syncthreads();
    if (threadIdx.x == 0) {
        __threadfence();
        if (atomicAdd(&g_arrive, 1u) == NBLK - 1u) {
            g_arrive = 0u;
            __threadfence();
            atomicExch(&g_release, gen);
        } else {
            unsigned v;
            do {
                asm volatile("ld.acquire.gpu.b32 %0, [%1];" : "=r"(v) : "l"(&g_release));
            } while (v < gen);
        }
    }
    __syncthreads();
}

// ---------------- packed f32x2 helpers ----------------
__device__ __forceinline__ void fma2(ull &d, ull a, ull b) {
    asm("fma.rn.f32x2 %0, %1, %2, %0;" : "+l"(d) : "l"(a), "l"(b));
}
__device__ __forceinline__ ull splat(float x) {
    ull r; asm("mov.b64 %0, {%1, %1};" : "=l"(r) : "f"(x)); return r;
}

// ---------------- GEMM tile 96x64 (128 tiles total), micro 6x4, dbl-buffered
// MODE 0: g_T  = g_P @ D2                         (A=P lda=512, B=D2, K=512)
// MODE 1: g_Km = exp((2*(D1@g_T) - t1 - t2)*EPSI) (A=D1 lda=768, B=T,  K=768)
// MODE 2: g_cp[tile] = sum((D1@g_P)_tile .* g_T_tile)
template<int MODE>
__device__ void gemm_tile(int tile, const float* __restrict__ D1,
                          const float* __restrict__ D2,
                          float* As, float* Bs, float* red) {
    const int Kd  = (MODE == 0) ? N_ : M_;
    const int lda = (MODE == 0) ? N_ : M_;
    int b = tile >> 6;
    int r = tile & 63;
    int row0 = (r >> 3) * 96;
    int col0 = (r & 7) * 64;
    const float* A  = (MODE == 0) ? (g_P + (size_t)b*MN_) : (D1 + (size_t)b*M_*M_);
    const float* Bm = (MODE == 0) ? (D2 + (size_t)b*(size_t)N_*N_)
                    : (MODE == 1) ? (g_T + (size_t)b*MN_)
                                  : (g_P + (size_t)b*MN_);
    int tid = threadIdx.x;
    int tx = tid & 15, ty = tid >> 4;
    int brow = tid >> 4, bq = tid & 15;

    // A loader: 3 float2 per thread covers 96x16
    int lr[3], lk[3];
    const float* ApL[3];
    #pragma unroll
    for (int j = 0; j < 3; j++) {
        int idx = tid + 256*j;
        lr[j] = idx >> 3;
        lk[j] = (idx & 7) * 2;
        ApL[j] = A + (size_t)(row0 + lr[j])*lda + lk[j];
    }
    const float* BpL = Bm + (size_t)brow*N_ + col0 + bq*4;

    ull acc[3][4];
    #pragma unroll
    for (int i = 0; i < 3; i++)
        #pragma unroll
        for (int j = 0; j < 4; j++) acc[i][j] = 0ull;

    float2 pa[3]; float4 pb;
    #pragma unroll
    for (int j = 0; j < 3; j++) pa[j] = *(const float2*)(ApL[j]);
    pb = *(const float4*)(BpL);

    int buf = 0;
    for (int k0 = 0; k0 < Kd; k0 += 16) {
        float* Asb = As + buf*AS_BUF;
        float* Bsb = Bs + buf*BS_BUF;
        #pragma unroll
        for (int j = 0; j < 3; j++) {
            Asb[lk[j]*AS_STRIDE + lr[j]]       = pa[j].x;
            Asb[(lk[j]+1)*AS_STRIDE + lr[j]]   = pa[j].y;
        }
        *(float4*)&Bsb[brow*64 + bq*4] = pb;
        if (k0 + 16 < Kd) {
            #pragma unroll
            for (int j = 0; j < 3; j++) pa[j] = *(const float2*)(ApL[j] + k0 + 16);
            pb = *(const float4*)(BpL + (size_t)(k0+16)*N_);
        }
        __syncthreads();
        #pragma unroll
        for (int k = 0; k < 16; k++) {
            const float* ap = Asb + k*AS_STRIDE + ty*6;
            ull a01 = *(const ull*)(ap);
            ull a23 = *(const ull*)(ap + 2);
            ull a45 = *(const ull*)(ap + 4);
            float4 b4 = *(const float4*)&Bsb[k*64 + tx*4];
            ull b0 = splat(b4.x), b1 = splat(b4.y), b2 = splat(b4.z), b3 = splat(b4.w);
            fma2(acc[0][0], a01, b0); fma2(acc[0][1], a01, b1);
            fma2(acc[0][2], a01, b2); fma2(acc[0][3], a01, b3);
            fma2(acc[1][0], a23, b0); fma2(acc[1][1], a23, b1);
            fma2(acc[1][2], a23, b2); fma2(acc[1][3], a23, b3);
            fma2(acc[2][0], a45, b0); fma2(acc[2][1], a45, b1);
            fma2(acc[2][2], a45, b2); fma2(acc[2][3], a45, b3);
        }
        buf ^= 1;
    }

    float cS[6][4];
    #pragma unroll
    for (int p = 0; p < 3; p++)
        #pragma unroll
        for (int j = 0; j < 4; j++) {
            union { ull u; float f[2]; } cv; cv.u = acc[p][j];
            cS[2*p][j]   = cv.f[0];
            cS[2*p+1][j] = cv.f[1];
        }

    if (MODE == 0) {
        float* Cb = g_T + (size_t)b*MN_;
        #pragma unroll
        for (int rr = 0; rr < 6; rr++) {
            int row = row0 + ty*6 + rr;
            float4 v = make_float4(cS[rr][0], cS[rr][1], cS[rr][2], cS[rr][3]);
            *(float4*)(Cb + (size_t)row*N_ + col0 + tx*4) = v;
        }
    } else if (MODE == 1) {
        float* Cb = g_Km + (size_t)b*MN_;
        const float* t1b = g_t1 + b*M_;
        const float* t2b = g_t2 + b*N_;
        float t20 = t2b[col0+tx*4+0], t21 = t2b[col0+tx*4+1];
        float t22 = t2b[col0+tx*4+2], t23 = t2b[col0+tx*4+3];
        #pragma unroll
        for (int rr = 0; rr < 6; rr++) {
            int row = row0 + ty*6 + rr;
            float t1v = t1b[row];
            float4 v;
            v.x = __expf((2.0f*cS[rr][0] - t1v - t20) * EPSI);
            v.y = __expf((2.0f*cS[rr][1] - t1v - t21) * EPSI);
            v.z = __expf((2.0f*cS[rr][2] - t1v - t22) * EPSI);
            v.w = __expf((2.0f*cS[rr][3] - t1v - t23) * EPSI);
            *(float4*)(Cb + (size_t)row*N_ + col0 + tx*4) = v;
        }
    } else {
        const float* Tb = g_T + (size_t)b*MN_;
        float local = 0.f;
        #pragma unroll
        for (int rr = 0; rr < 6; rr++) {
            int row = row0 + ty*6 + rr;
            float4 tv = *(const float4*)(Tb + (size_t)row*N_ + col0 + tx*4);
            local += cS[rr][0]*tv.x + cS[rr][1]*tv.y + cS[rr][2]*tv.z + cS[rr][3]*tv.w;
        }
        red[tid] = local;
        __syncthreads();
        for (int st = 128; st; st >>= 1) {
            if (tid < st) red[tid] += red[tid + st];
            __syncthreads();
        }
        if (!tid) g_cp[tile] = red[0];
    }
}

// ---------------- t1 = (D1.^2) @ rm  (all blocks, own 12 rows) -------------
__device__ void sqmv_t1(const float* __restrict__ D1, int bid, int wid, int lane) {
    int nrows = (wid < 4) ? 2 : 1;
    for (int rr = 0; rr < nrows; rr++) {
        int fi = bid*RPB + wid + rr*8;
        int b2 = fi >= M_;
        int i  = fi - b2*M_;
        const float4* row = (const float4*)(D1 + ((size_t)b2*M_ + i)*M_);
        const float4* rmb = (const float4*)(g_rm + b2*M_);
        float s = 0.f;
        for (int q = lane; q < 192; q += 32) {
            float4 v  = row[q];
            float4 r4 = rmb[q];
            s += v.x*v.x*r4.x + v.y*v.y*r4.y + v.z*v.z*r4.z + v.w*v.w*r4.w;
        }
        #pragma unroll
        for (int o = 16; o; o >>= 1) s += __shfl_xor_sync(0xffffffffu, s, o);
        if (!lane) g_t1[fi] = s;
    }
}

// ---------------- persistent mega-kernel ----------------
__global__ void __launch_bounds__(NTHR)
gw_kernel(const float* __restrict__ D1, const float* __restrict__ D2,
          float* __restrict__ out, int out_size) {
    __shared__ float sKs[RPB*N_];        // 24 KB K-row cache
    __shared__ float As[2*AS_BUF];       // 12.25 KB
    __shared__ float Bs[2*BS_BUF];       // 8 KB
    __shared__ float tS[N_];             // 2 KB
    __shared__ float sRed[NTHR];
    __shared__ float sLoc[RPB];

    int bid = blockIdx.x, tid = threadIdx.x;
    int wid = tid >> 5, lane = tid & 31;
    unsigned gen = 0;
    int bb = bid >> 6;                          // batch (64 blocks each)
    size_t rowbase = (size_t)bid * (RPB*N_);

    // ---------- Phase I: init P, rm, t2, csum[0] ----------
    for (int idx = tid; idx < RPB*N_; idx += NTHR) g_P[rowbase + idx] = AW*BW;
    if (tid < RPB) g_rm[bid*RPB + tid] = AW;
    {
        int gw2 = bid*8 + wid;                  // 0..1023
        int b2 = gw2 >> 9, j = gw2 & 511;
        const float4* row = (const float4*)(D2 + ((size_t)b2*N_ + j)*N_);
        float s = 0.f;
        for (int q = lane; q < 128; q += 32) {
            float4 v = row[q];
            s += v.x*v.x + v.y*v.y + v.z*v.z + v.w*v.w;
        }
        #pragma unroll
        for (int o = 16; o; o >>= 1) s += __shfl_xor_sync(0xffffffffu, s, o);
        if (!lane) g_t2[gw2] = BW * s;
    }
    if (bid == 0)
        for (int idx = tid; idx < B_*N_; idx += NTHR) g_csum[0][idx] = 0.f;
    gsync(gen);

    int git = 0;
    for (int outer = 0; outer < 10; outer++) {
        // Phase A: T = P@D2 (all 128 blocks, 1 tile each) + t1 sqmv
        gemm_tile<0>(bid, D1, D2, As, Bs, sRed);
        sqmv_t1(D1, bid, wid, lane);
        gsync(gen);

        // Phase B: Km = exp(...)
        gemm_tile<1>(bid, D1, D2, As, Bs, sRed);
        gsync(gen);

        // Sinkhorn: 20 iterations, 1 barrier each
        for (int it = 0; it < 20; it++, git++) {
            if (it == 0) {
                const float4* src = (const float4*)(g_Km + rowbase);
                float4* dst = (float4*)sKs;
                for (int idx = tid; idx < RPB*N_/4; idx += NTHR) dst[idx] = src[idx];
                __syncthreads();
            }
            // u-dots: rows 0..7 (all warps), rows 8..11 (warps 0..3)
            {
                int r = wid;
                float s = 0.f;
                if (it == 0) {
                    for (int q = lane; q < 128; q += 32) {
                        float4 v = *(const float4*)&sKs[r*N_ + q*4];
                        s += v.x + v.y + v.z + v.w;
                    }
                } else {
                    for (int q = lane; q < 128; q += 32) {
                        float4 v  = *(const float4*)&sKs[r*N_ + q*4];
                        float4 t4 = *(const float4*)&tS[q*4];
                        s += v.x*t4.x + v.y*t4.y + v.z*t4.z + v.w*t4.w;
                    }
                }
                #pragma unroll
                for (int o = 16; o; o >>= 1) s += __shfl_xor_sync(0xffffffffu, s, o);
                if (!lane) sLoc[r] = __fdividef(AW, s);
            }
            if (wid < 4) {
                int r = 8 + wid;
                float s = 0.f;
                if (it == 0) {
                    for (int q = lane; q < 128; q += 32) {
                        float4 v = *(const float4*)&sKs[r*N_ + q*4];
                        s += v.x + v.y + v.z + v.w;
                    }
                } else {
                    for (int q = lane; q < 128; q += 32) {
                        float4 v  = *(const float4*)&sKs[r*N_ + q*4];
                        float4 t4 = *(const float4*)&tS[q*4];
                        s += v.x*t4.x + v.y*t4.y + v.z*t4.z + v.w*t4.w;
                    }
                }
                #pragma unroll
                for (int o = 16; o; o >>= 1) s += __shfl_xor_sync(0xffffffffu, s, o);
                if (!lane) sLoc[r] = __fdividef(AW, s);
            }
            __syncthreads();
            // column partials -> atomic accumulate; zero buffer for git+1
            {
                float a0 = 0.f, a1 = 0.f;
                #pragma unroll
                for (int rr = 0; rr < RPB; rr++) {
                    float sv = sLoc[rr];
                    a0 += sKs[rr*N_ + tid]       * sv;
                    a1 += sKs[rr*N_ + tid + 256] * sv;
                }
                int p = git % 3;
                atomicAdd(&g_csum[p][bb*N_ + tid],       a0);
                atomicAdd(&g_csum[p][bb*N_ + tid + 256], a1);
                int pn = (p + 1 == 3) ? 0 : p + 1;
                if (tid < 8) g_csum[pn][bb*N_ + (bid & 63)*8 + tid] = 0.f;
            }
            gsync(gen);
            // t recompute (redundant per block, into SMEM)
            {
                int p = git % 3;
                tS[tid]       = __fdividef(BW, g_csum[p][bb*N_ + tid]);
                tS[tid + 256] = __fdividef(BW, g_csum[p][bb*N_ + tid + 256]);
            }
            __syncthreads();
        }

        // P update + row masses
        {
            int r = wid;
            float s = 0.f;
            for (int q = lane; q < 128; q += 32) {
                float4 v  = *(const float4*)&sKs[r*N_ + q*4];
                float4 t4 = *(const float4*)&tS[q*4];
                s += v.x*t4.x + v.y*t4.y + v.z*t4.z + v.w*t4.w;
            }
            #pragma unroll
            for (int o = 16; o; o >>= 1) s += __shfl_xor_sync(0xffffffffu, s, o);
            if (!lane) g_rm[bid*RPB + r] = sLoc[r] * s;
        }
        if (wid < 4) {
            int r = 8 + wid;
            float s = 0.f;
            for (int q = lane; q < 128; q += 32) {
                float4 v  = *(const float4*)&sKs[r*N_ + q*4];
                float4 t4 = *(const float4*)&tS[q*4];
                s += v.x*t4.x + v.y*t4.y + v.z*t4.z + v.w*t4.w;
            }
            #pragma unroll
            for (int o = 16; o; o >>= 1) s += __shfl_xor_sync(0xffffffffu, s, o);
            if (!lane) g_rm[bid*RPB + r] = sLoc[r] * s;
        }
        #pragma unroll
        for (int rr = 0; rr < RPB; rr++) {
            float sv = sLoc[rr];
            g_P[rowbase + rr*N_ + tid]       = sv * sKs[rr*N_ + tid]       * tS[tid];
            g_P[rowbase + rr*N_ + tid + 256] = sv * sKs[rr*N_ + tid + 256] * tS[tid + 256];
        }
        gsync(gen);
    }

    // ---------- Final cost ----------
    // F1: T = P@D2 (final P) + t1 with final rm
    gemm_tile<0>(bid, D1, D2, As, Bs, sRed);
    sqmv_t1(D1, bid, wid, lane);
    gsync(gen);

    // F2: cross partials (all blocks) + scalar dots (blocks 0, 1)
    gemm_tile<2>(bid, D1, D2, As, Bs, sRed);
    __syncthreads();
    if (bid == 0) {
        for (int b2 = 0; b2 < 2; b2++) {
            float s = 0.f;
            for (int i = tid; i < M_; i += NTHR) s += g_rm[b2*M_ + i] * g_t1[b2*M_ + i];
            sRed[tid] = s;
            __syncthreads();
            for (int st = 128; st; st >>= 1) {
                if (tid < st) sRed[tid] += sRed[tid + st];
                __syncthreads();
            }
            if (!tid) g_acc[b2] = sRed[0];
            __syncthreads();
        }
    } else if (bid == 1) {
        for (int b2 = 0; b2 < 2; b2++) {
            float s = 0.f;
            for (int j = tid; j < N_; j += NTHR) s += g_t2[b2*N_ + j];
            sRed[tid] = s;
            __syncthreads();
            for (int st = 128; st; st >>= 1) {
                if (tid < st) sRed[tid] += sRed[tid + st];
                __syncthreads();
            }
            if (!tid) g_acc[2 + b2] = BW * sRed[0];
            __syncthreads();
        }
    }
    gsync(gen);

    // F3: outputs
    if (bid == 0 && tid < 2) {
        float cr = 0.f;
        for (int t = 0; t < 64; t++) cr += g_cp[tid*64 + t];
        out[tid] = g_acc[tid] + g_acc[2 + tid] - 2.0f*cr;
    }
    if (out_size > 2) {
        const float2* src = (const float2*)(g_P + rowbase);
        float2* dst = (float2*)(out + 2 + rowbase);
        for (int idx = tid; idx < RPB*N_/2; idx += NTHR) dst[idx] = src[idx];
    }
}

// ---------------- host driver ----------------
extern "C" void kernel_launch(void* const* d_in, const int* in_sizes, int n_in,
                              void* d_out, int out_size) {
    const float* D1 = (const float*)d_in[0];
    const float* D2 = (const float*)d_in[1];
    if (n_in >= 2 && in_sizes[0] == B_*N_*N_ && in_sizes[1] == B_*M_*M_) {
        const float* tmp = D1; D1 = D2; D2 = tmp;
    }
    float* out = (float*)d_out;

    reset_kernel<<<1, 1>>>();
    gw_kernel<<<NBLK, NTHR>>>(D1, D2, out, out_size);
}

// round 5
// speedup vs baseline: 3.6517x; 1.0904x over previous
#include <cuda_runtime.h>

#define NBLK 128
#define NTHR 384
#define B_ 2
#define M_ 768
#define N_ 512
#define MN_ (M_*N_)
#define AW (1.0f/768.0f)
#define BW (1.0f/512.0f)
#define EPSI 20.0f
#define RPB 12            // rows per block: 128*12 = 1536 = B*M
#define AS_STRIDE 98      // padded 96+2
#define AS_BUF (16*AS_STRIDE)
#define BS_BUF (16*64)

typedef unsigned long long ull;

// ---------------- device scratch ----------------
__device__ float g_P [B_*MN_];
__device__ float g_Km[B_*MN_];
__device__ float g_T [B_*MN_];
__device__ float g_rm[B_*M_];
__device__ float g_t1[B_*M_];
__device__ float g_t2[B_*N_];
__device__ float g_csum[3][B_*N_];   // triple-buffered atomic column sums
__device__ float g_cp[128];
__device__ float g_acc[4];
__device__ unsigned g_bar[64];       // [0] batch0 counter, [32] batch1 (128B apart)

__global__ void reset_kernel() { g_bar[0] = 0u; g_bar[32] = 0u; }

// ------- per-batch count barrier: release-arrive, acquire-poll, no reset ----
__device__ __forceinline__ void gsync(unsigned &gen, unsigned* ctr) {
    ++gen;
    __syncthreads();
    if (threadIdx.x == 0) {
        asm volatile("red.release.gpu.global.add.u32 [%0], %1;"
                     :: "l"(ctr), "r"(1u) : "memory");
        unsigned target = gen * 64u;
        unsigned v;
        do {
            asm volatile("ld.acquire.gpu.global.b32 %0, [%1];"
                         : "=r"(v) : "l"(ctr) : "memory");
        } while (v < target);
    }
    __syncthreads();
}

// ---------------- packed f32x2 helpers ----------------
__device__ __forceinline__ void fma2(ull &d, ull a, ull b) {
    asm("fma.rn.f32x2 %0, %1, %2, %0;" : "+l"(d) : "l"(a), "l"(b));
}
__device__ __forceinline__ ull splat(float x) {
    ull r; asm("mov.b64 %0, {%1, %1};" : "=l"(r) : "f"(x)); return r;
}

// ---------------- GEMM tile 96x64 (128 tiles), 384 thr, micro 4x4 ----------
// MODE 0: g_T  = g_P @ D2                         (A=P lda=512, B=D2, K=512)
// MODE 1: g_Km = exp((2*(D1@g_T) - t1 - t2)*EPSI) (A=D1 lda=768, B=T,  K=768)
// MODE 2: g_cp[tile] = sum((D1@g_P)_tile .* g_T_tile)
template<int MODE>
__device__ void gemm_tile(int tile, const float* __restrict__ D1,
                          const float* __restrict__ D2,
                          float* As, float* Bs, float* red) {
    const int Kd  = (MODE == 0) ? N_ : M_;
    const int lda = (MODE == 0) ? N_ : M_;
    int b = tile >> 6;
    int r = tile & 63;
    int row0 = (r >> 3) * 96;
    int col0 = (r & 7) * 64;
    const float* A  = (MODE == 0) ? (g_P + (size_t)b*MN_) : (D1 + (size_t)b*M_*M_);
    const float* Bm = (MODE == 0) ? (D2 + (size_t)b*(size_t)N_*N_)
                    : (MODE == 1) ? (g_T + (size_t)b*MN_)
                                  : (g_P + (size_t)b*MN_);
    int tid = threadIdx.x;
    int tx = tid & 15, ty = tid >> 4;          // ty 0..23 -> rows ty*4..+3

    // A loader: 384 threads x float4 covers 96x16
    int lr = tid >> 2;                          // 0..95
    int lk = (tid & 3) * 4;                     // 0,4,8,12
    const float* ApL = A + (size_t)(row0 + lr)*lda + lk;
    // B loader: first 256 threads x float4 covers 16x64
    int brow = tid >> 4, bq = tid & 15;
    const float* BpL = Bm + (size_t)brow*N_ + col0 + bq*4;

    ull acc[2][4];
    #pragma unroll
    for (int i = 0; i < 2; i++)
        #pragma unroll
        for (int j = 0; j < 4; j++) acc[i][j] = 0ull;

    float4 pa = *(const float4*)(ApL);
    float4 pb;
    if (tid < 256) pb = *(const float4*)(BpL);

    int buf = 0;
    for (int k0 = 0; k0 < Kd; k0 += 16) {
        float* Asb = As + buf*AS_BUF;
        float* Bsb = Bs + buf*BS_BUF;
        Asb[(lk+0)*AS_STRIDE + lr] = pa.x;
        Asb[(lk+1)*AS_STRIDE + lr] = pa.y;
        Asb[(lk+2)*AS_STRIDE + lr] = pa.z;
        Asb[(lk+3)*AS_STRIDE + lr] = pa.w;
        if (tid < 256) *(float4*)&Bsb[brow*64 + bq*4] = pb;
        if (k0 + 16 < Kd) {
            pa = *(const float4*)(ApL + k0 + 16);
            if (tid < 256) pb = *(const float4*)(BpL + (size_t)(k0+16)*N_);
        }
        __syncthreads();
        #pragma unroll
        for (int k = 0; k < 16; k++) {
            const float* ap = Asb + k*AS_STRIDE + ty*4;
            ull a01 = *(const ull*)(ap);
            ull a23 = *(const ull*)(ap + 2);
            float4 b4 = *(const float4*)&Bsb[k*64 + tx*4];
            ull b0 = splat(b4.x), b1 = splat(b4.y), b2 = splat(b4.z), b3 = splat(b4.w);
            fma2(acc[0][0], a01, b0); fma2(acc[0][1], a01, b1);
            fma2(acc[0][2], a01, b2); fma2(acc[0][3], a01, b3);
            fma2(acc[1][0], a23, b0); fma2(acc[1][1], a23, b1);
            fma2(acc[1][2], a23, b2); fma2(acc[1][3], a23, b3);
        }
        buf ^= 1;
    }

    float cS[4][4];
    #pragma unroll
    for (int p = 0; p < 2; p++)
        #pragma unroll
        for (int j = 0; j < 4; j++) {
            union { ull u; float f[2]; } cv; cv.u = acc[p][j];
            cS[2*p][j]   = cv.f[0];
            cS[2*p+1][j] = cv.f[1];
        }

    if (MODE == 0) {
        float* Cb = g_T + (size_t)b*MN_;
        #pragma unroll
        for (int rr = 0; rr < 4; rr++) {
            int row = row0 + ty*4 + rr;
            float4 v = make_float4(cS[rr][0], cS[rr][1], cS[rr][2], cS[rr][3]);
            *(float4*)(Cb + (size_t)row*N_ + col0 + tx*4) = v;
        }
    } else if (MODE == 1) {
        float* Cb = g_Km + (size_t)b*MN_;
        const float* t1b = g_t1 + b*M_;
        const float* t2b = g_t2 + b*N_;
        float t20 = t2b[col0+tx*4+0], t21 = t2b[col0+tx*4+1];
        float t22 = t2b[col0+tx*4+2], t23 = t2b[col0+tx*4+3];
        #pragma unroll
        for (int rr = 0; rr < 4; rr++) {
            int row = row0 + ty*4 + rr;
            float t1v = t1b[row];
            float4 v;
            v.x = __expf((2.0f*cS[rr][0] - t1v - t20) * EPSI);
            v.y = __expf((2.0f*cS[rr][1] - t1v - t21) * EPSI);
            v.z = __expf((2.0f*cS[rr][2] - t1v - t22) * EPSI);
            v.w = __expf((2.0f*cS[rr][3] - t1v - t23) * EPSI);
            *(float4*)(Cb + (size_t)row*N_ + col0 + tx*4) = v;
        }
    } else {
        const float* Tb = g_T + (size_t)b*MN_;
        float local = 0.f;
        #pragma unroll
        for (int rr = 0; rr < 4; rr++) {
            int row = row0 + ty*4 + rr;
            float4 tv = *(const float4*)(Tb + (size_t)row*N_ + col0 + tx*4);
            local += cS[rr][0]*tv.x + cS[rr][1]*tv.y + cS[rr][2]*tv.z + cS[rr][3]*tv.w;
        }
        red[tid] = local;
        __syncthreads();
        if (tid < 128) red[tid] += red[tid + 128] + red[tid + 256];
        __syncthreads();
        for (int st = 64; st; st >>= 1) {
            if (tid < st) red[tid] += red[tid + st];
            __syncthreads();
        }
        if (!tid) g_cp[tile] = red[0];
    }
}

// ---------------- t1 = (D1.^2) @ rm  (warp per row, 12 warps) --------------
__device__ void sqmv_t1(const float* __restrict__ D1, int bid, int wid, int lane) {
    int fi = bid*RPB + wid;
    int b2 = fi >= M_;
    int i  = fi - b2*M_;
    const float4* row = (const float4*)(D1 + ((size_t)b2*M_ + i)*M_);
    const float4* rmb = (const float4*)(g_rm + b2*M_);
    float s = 0.f;
    for (int q = lane; q < 192; q += 32) {
        float4 v  = row[q];
        float4 r4 = rmb[q];
        s += v.x*v.x*r4.x + v.y*v.y*r4.y + v.z*v.z*r4.z + v.w*v.w*r4.w;
    }
    #pragma unroll
    for (int o = 16; o; o >>= 1) s += __shfl_xor_sync(0xffffffffu, s, o);
    if (!lane) g_t1[fi] = s;
}

// ---------------- persistent mega-kernel ----------------
__global__ void __launch_bounds__(NTHR)
gw_kernel(const float* __restrict__ D1, const float* __restrict__ D2,
          float* __restrict__ out, int out_size) {
    __shared__ float sKs[RPB*N_];        // 24 KB K-row cache
    __shared__ float As[2*AS_BUF];       // 12.25 KB
    __shared__ float Bs[2*BS_BUF];       // 8 KB
    __shared__ float tS[N_];             // 2 KB
    __shared__ float sRed[NTHR];
    __shared__ float sLoc[RPB];

    int bid = blockIdx.x, tid = threadIdx.x;
    int wid = tid >> 5, lane = tid & 31;
    unsigned gen = 0;
    int bb = bid >> 6;                          // batch (64 blocks each)
    unsigned* ctr = &g_bar[bb*32];
    size_t rowbase = (size_t)bid * (RPB*N_);

    // ---------- Phase I: init P, rm, t2, csum[0] ----------
    for (int idx = tid; idx < RPB*N_; idx += NTHR) g_P[rowbase + idx] = AW*BW;
    if (tid < RPB) g_rm[bid*RPB + tid] = AW;
    if (wid < 8) {
        int gw2 = bid*8 + wid;                  // 0..1023
        int b2 = gw2 >> 9, j = gw2 & 511;
        const float4* row = (const float4*)(D2 + ((size_t)b2*N_ + j)*N_);
        float s = 0.f;
        for (int q = lane; q < 128; q += 32) {
            float4 v = row[q];
            s += v.x*v.x + v.y*v.y + v.z*v.z + v.w*v.w;
        }
        #pragma unroll
        for (int o = 16; o; o >>= 1) s += __shfl_xor_sync(0xffffffffu, s, o);
        if (!lane) g_t2[gw2] = BW * s;
    }
    if ((bid & 63) == 0)
        for (int idx = tid; idx < N_; idx += NTHR) g_csum[0][bb*N_ + idx] = 0.f;
    gsync(gen, ctr);

    int git = 0;
    for (int outer = 0; outer < 10; outer++) {
        // Phase A: T = P@D2 (1 tile/block) + t1 sqmv
        gemm_tile<0>(bid, D1, D2, As, Bs, sRed);
        sqmv_t1(D1, bid, wid, lane);
        gsync(gen, ctr);

        // Phase B: Km = exp(...)
        gemm_tile<1>(bid, D1, D2, As, Bs, sRed);
        gsync(gen, ctr);

        // Sinkhorn: 20 iterations, 1 barrier each
        for (int it = 0; it < 20; it++, git++) {
            if (it == 0) {
                const float4* src = (const float4*)(g_Km + rowbase);
                float4* dst = (float4*)sKs;
                for (int idx = tid; idx < RPB*N_/4; idx += NTHR) dst[idx] = src[idx];
                __syncthreads();
            }
            // u-dot: warp wid handles row wid
            {
                float s = 0.f;
                if (it == 0) {
                    for (int q = lane; q < 128; q += 32) {
                        float4 v = *(const float4*)&sKs[wid*N_ + q*4];
                        s += v.x + v.y + v.z + v.w;
                    }
                } else {
                    for (int q = lane; q < 128; q += 32) {
                        float4 v  = *(const float4*)&sKs[wid*N_ + q*4];
                        float4 t4 = *(const float4*)&tS[q*4];
                        s += v.x*t4.x + v.y*t4.y + v.z*t4.z + v.w*t4.w;
                    }
                }
                #pragma unroll
                for (int o = 16; o; o >>= 1) s += __shfl_xor_sync(0xffffffffu, s, o);
                if (!lane) sLoc[wid] = __fdividef(AW, s);
            }
            __syncthreads();
            // column partials -> atomic accumulate; zero buffer for git+1
            {
                int p = git % 3;
                float a0 = 0.f;
                #pragma unroll
                for (int rr = 0; rr < RPB; rr++)
                    a0 += sKs[rr*N_ + tid] * sLoc[rr];
                atomicAdd(&g_csum[p][bb*N_ + tid], a0);
                if (tid < 128) {
                    float a1 = 0.f;
                    #pragma unroll
                    for (int rr = 0; rr < RPB; rr++)
                        a1 += sKs[rr*N_ + tid + 384] * sLoc[rr];
                    atomicAdd(&g_csum[p][bb*N_ + tid + 384], a1);
                }
                int pn = (p + 1 == 3) ? 0 : p + 1;
                if (tid < 8) g_csum[pn][bb*N_ + (bid & 63)*8 + tid] = 0.f;
            }
            gsync(gen, ctr);
            // t recompute (redundant per block, into SMEM)
            {
                int p = git % 3;
                tS[tid] = __fdividef(BW, g_csum[p][bb*N_ + tid]);
                if (tid < 128)
                    tS[tid + 384] = __fdividef(BW, g_csum[p][bb*N_ + tid + 384]);
            }
            __syncthreads();
        }

        // P update + row masses (warp per row)
        {
            float s = 0.f;
            for (int q = lane; q < 128; q += 32) {
                float4 v  = *(const float4*)&sKs[wid*N_ + q*4];
                float4 t4 = *(const float4*)&tS[q*4];
                s += v.x*t4.x + v.y*t4.y + v.z*t4.z + v.w*t4.w;
            }
            #pragma unroll
            for (int o = 16; o; o >>= 1) s += __shfl_xor_sync(0xffffffffu, s, o);
            if (!lane) g_rm[bid*RPB + wid] = sLoc[wid] * s;
        }
        for (int c = tid; c < RPB*N_; c += NTHR) {
            int rr = c >> 9, j = c & 511;
            g_P[rowbase + c] = sLoc[rr] * sKs[c] * tS[j];
        }
        gsync(gen, ctr);
    }

    // ---------- Final cost ----------
    // F1: T = P@D2 (final P) + t1 with final rm
    gemm_tile<0>(bid, D1, D2, As, Bs, sRed);
    sqmv_t1(D1, bid, wid, lane);
    gsync(gen, ctr);

    // F2: cross partials (all blocks) + per-batch scalar dots
    gemm_tile<2>(bid, D1, D2, As, Bs, sRed);
    __syncthreads();
    if ((bid & 63) == 0) {                 // blocks 0 and 64: rm . t1
        int b2 = bb;
        float s = 0.f;
        for (int i = tid; i < M_; i += NTHR) s += g_rm[b2*M_ + i] * g_t1[b2*M_ + i];
        sRed[tid] = s;
        __syncthreads();
        if (tid < 128) sRed[tid] += sRed[tid + 128] + sRed[tid + 256];
        __syncthreads();
        for (int st = 64; st; st >>= 1) {
            if (tid < st) sRed[tid] += sRed[tid + st];
            __syncthreads();
        }
        if (!tid) g_acc[b2] = sRed[0];
    } else if ((bid & 63) == 1) {          // blocks 1 and 65: sum t2 * BW
        int b2 = bb;
        float s = 0.f;
        for (int j = tid; j < N_; j += NTHR) s += g_t2[b2*N_ + j];
        sRed[tid] = s;
        __syncthreads();
        if (tid < 128) sRed[tid] += sRed[tid + 128] + sRed[tid + 256];
        __syncthreads();
        for (int st = 64; st; st >>= 1) {
            if (tid < st) sRed[tid] += sRed[tid + st];
            __syncthreads();
        }
        if (!tid) g_acc[2 + b2] = BW * sRed[0];
    }
    gsync(gen, ctr);

    // F3: outputs (block 0 -> out[0], block 64 -> out[1]); P copy (own rows)
    if ((bid & 63) == 0 && tid == 0) {
        float cr = 0.f;
        for (int t = 0; t < 64; t++) cr += g_cp[bb*64 + t];
        out[bb] = g_acc[bb] + g_acc[2 + bb] - 2.0f*cr;
    }
    if (out_size > 2) {
        const float2* src = (const float2*)(g_P + rowbase);
        float2* dst = (float2*)(out + 2 + rowbase);
        for (int idx = tid; idx < RPB*N_/2; idx += NTHR) dst[idx] = src[idx];
    }
}

// ---------------- host driver ----------------
extern "C" void kernel_launch(void* const* d_in, const int* in_sizes, int n_in,
                              void* d_out, int out_size) {
    const float* D1 = (const float*)d_in[0];
    const float* D2 = (const float*)d_in[1];
    if (n_in >= 2 && in_sizes[0] == B_*N_*N_ && in_sizes[1] == B_*M_*M_) {
        const float* tmp = D1; D1 = D2; D2 = tmp;
    }
    float* out = (float*)d_out;

    reset_kernel<<<1, 1>>>();
    gw_kernel<<<NBLK, NTHR>>>(D1, D2, out, out_size);
}